// round 11
// baseline (speedup 1.0000x reference)
#include <cuda_runtime.h>
#include <cuda_fp16.h>
#include <cstdint>

// 3x3 s1 p1 conv, NCHW fp32 via mma.sync.m16n8k16 FP16 (f32 accumulate).
// R10 (92.6 us, 3 CTAs/SM) + two overhead cuts:
//  - ring of 12 input-row slots -> ONE __syncthreads per 4-row phase (4/CTA):
//    build(p+1) rows y+5..y+8 never alias the slowest warp's reads y-1..y+4
//    (span 10 < 12), so the pre-build barrier is dropped.
//  - vectorized build: 2x LDG.128 + 1x STS.128 per thread per row (edges by
//    32 threads); layout shifted +3 words for 16B-aligned STS.128.
// CTA = 64-px x-strip x 16 output rows x 1 image; 256 thr / 8 warps.
// Warp = 1 m-tile (16 px) x 2 n-tiles (16 oc) x 4 rows per phase (C=32 regs).
// A: half2-packed [ic/2][px], stride 72 (conflict-free LDS.32 gathers).
// Smem 73.7 KB -> 3 CTAs/SM. Direct sector-perfect STG.32 epilogue.

#define HW     256
#define ICN    32
#define OCN    32
#define SW     64            // strip width
#define YCH    16            // output rows per CTA
#define STRIDE 72            // u32 per kp row (==8 mod 32 -> conflict-free)
#define KPN    16            // ic/2 packed rows
#define SLOT_U (KPN * STRIDE)              // 1152 u32 = 4608 B
#define B_BYTES (9 * 2 * 4 * 32 * 8)       // 18432
#define SM_A    B_BYTES
#define NSLOT   12
#define SMEM_TOTAL (B_BYTES + NSLOT * SLOT_U * 4)   // 73728 B

__device__ __forceinline__ uint32_t pack_h2(float a, float b) {
    uint32_t r;
    asm("cvt.rn.f16x2.f32 %0, %2, %1;" : "=r"(r) : "f"(a), "f"(b));
    return r;   // lo half = a, hi half = b
}

__device__ __forceinline__ void mma16(float c[4], uint32_t a0, uint32_t a1,
                                      uint32_t a2, uint32_t a3, uint2 b) {
    asm volatile(
        "mma.sync.aligned.m16n8k16.row.col.f32.f16.f16.f32 "
        "{%0,%1,%2,%3},{%4,%5,%6,%7},{%8,%9},{%0,%1,%2,%3};"
        : "+f"(c[0]), "+f"(c[1]), "+f"(c[2]), "+f"(c[3])
        : "r"(a0), "r"(a1), "r"(a2), "r"(a3), "r"(b.x), "r"(b.y));
}

// Stage input row yin into ring slot (yin mod 12).
// Word layout: slot[kp*STRIDE + px + 3], px in 0..65 <-> gx = x0-1+px.
// Interior (all 256 thr): kp=tid>>4, px=1+4*(tid&15): 2x LDG.128 + 1x STS.128.
// Edges (tid<32): px=0 and px=65 scalar.
__device__ __forceinline__ void build_row(const float* __restrict__ xn, int yin,
                                          int x0, uint32_t* __restrict__ smA,
                                          int tid) {
    uint32_t* slot = smA + ((yin + NSLOT) % NSLOT) * SLOT_U;
    const bool yok = ((unsigned)yin < HW);
    const int kp = tid >> 4, gi = tid & 15;
    const int px = 1 + 4 * gi;                 // gx = x0 + 4*gi (16B aligned)
    float4 v0 = make_float4(0.f, 0.f, 0.f, 0.f), v1 = v0;
    if (yok) {
        const float* p = xn + (((size_t)kp * 2) << 16) + ((size_t)yin << 8)
                            + (x0 - 1 + px);
        v0 = *(const float4*)p;
        v1 = *(const float4*)(p + (1 << 16));
    }
    uint4 w;
    w.x = pack_h2(v0.x, v1.x);
    w.y = pack_h2(v0.y, v1.y);
    w.z = pack_h2(v0.z, v1.z);
    w.w = pack_h2(v0.w, v1.w);
    *(uint4*)(slot + kp * STRIDE + px + 3) = w;

    if (tid < 32) {
        const int kpe = tid & 15;
        const int pxe = (tid >> 4) ? 65 : 0;
        const int gxe = x0 - 1 + pxe;
        float a = 0.f, b = 0.f;
        if (yok && (unsigned)gxe < HW) {
            const float* p = xn + (((size_t)kpe * 2) << 16)
                               + ((size_t)yin << 8) + gxe;
            a = p[0];
            b = p[1 << 16];
        }
        slot[kpe * STRIDE + pxe + 3] = pack_h2(a, b);
    }
}

__global__ __launch_bounds__(256, 3)
void conv3x3_f16_r11_kernel(const float* __restrict__ xg,
                            const float* __restrict__ wg,
                            const float* __restrict__ bg,
                            float* __restrict__ out)
{
    extern __shared__ char smem[];
    uint32_t* smA = (uint32_t*)(smem + SM_A);
    const int tid  = threadIdx.x;
    const int warp = tid >> 5;
    const int lane = tid & 31;
    const int mt   = warp >> 1;     // m-tile 0..3
    const int nth  = warp & 1;      // n-tile half

    const int x0 = blockIdx.x * SW;
    const int y0 = blockIdx.y * YCH;
    const int n  = blockIdx.z;
    const float* xn = xg + (((size_t)n * ICN) << 16);

    // ---- Stage B (fragment order): 2304 uint2 frags, once per CTA
    #pragma unroll
    for (int it = 0; it < 9; it++) {
        int idx  = tid + it * 256;
        int l    = idx & 31;
        int nt   = (idx >> 5) & 3;
        int k0   = (idx >> 7) & 1;
        int tap  = idx >> 8;                    // dy*3+dx
        int oc   = nt * 8 + (l >> 2);
        int ic0  = k0 * 16 + (l & 3) * 2;
        const float* wp = wg + (size_t)oc * ICN * 9 + tap;
        uint2 w2;
        w2.x = pack_h2(wp[(size_t)ic0 * 9],       wp[(size_t)(ic0 + 1) * 9]);
        w2.y = pack_h2(wp[(size_t)(ic0 + 8) * 9], wp[(size_t)(ic0 + 9) * 9]);
        *(uint2*)(smem + ((((tap * 2 + k0) * 4 + nt) * 32 + l) << 3)) = w2;
    }

    // ---- Prologue rows y0-1, y0
    build_row(xn, y0 - 1, x0, smA, tid);
    build_row(xn, y0,     x0, smA, tid);

    const int t = lane & 3, g = lane >> 2;
    const uint2* bw = (const uint2*)smem + lane;
    const int gx = x0 + mt * 16 + g;
    const uint32_t lbase = t * STRIDE + mt * 16 + g + 3;   // +3 layout shift

    #pragma unroll 1
    for (int p = 0; p < YCH / 4; p++) {
        const int y = y0 + 4 * p;           // rows y .. y+3

        // build next 4 input rows (slots disjoint from any live reads; ring=12)
        build_row(xn, y + 1, x0, smA, tid);
        build_row(xn, y + 2, x0, smA, tid);
        build_row(xn, y + 3, x0, smA, tid);
        build_row(xn, y + 4, x0, smA, tid);
        __syncthreads();                    // the ONLY barrier per phase

        float c[4][2][4];
        #pragma unroll
        for (int r = 0; r < 4; r++)
            #pragma unroll
            for (int j = 0; j < 2; j++)
                #pragma unroll
                for (int i = 0; i < 4; i++) c[r][j][i] = 0.f;

        uint32_t so[6];
        #pragma unroll
        for (int i = 0; i < 6; i++)
            so[i] = ((y - 1 + i + NSLOT) % NSLOT) * SLOT_U + lbase;

        #pragma unroll
        for (int k0 = 0; k0 < 2; k0++) {
            #pragma unroll
            for (int dx = 0; dx < 3; dx++) {
                // cache 6 B frags (3 dy x 2 nt) in regs
                uint2 b[3][2];
                #pragma unroll
                for (int dy = 0; dy < 3; dy++)
                    #pragma unroll
                    for (int j = 0; j < 2; j++)
                        b[dy][j] = bw[(size_t)((((dy * 3 + dx) * 2 + k0) * 4
                                                + nth * 2 + j)) * 32];

                const int ao = k0 * 8 * STRIDE + dx;

                #pragma unroll
                for (int i = 0; i < 6; i++) {
                    const uint32_t* s = smA + so[i] + ao;
                    uint32_t a0 = s[0], a1 = s[8];
                    uint32_t a2 = s[4 * STRIDE], a3 = s[4 * STRIDE + 8];
                    #pragma unroll
                    for (int dy = 0; dy < 3; dy++) {
                        int rl = i - dy;
                        if (rl >= 0 && rl < 4) {
                            mma16(c[rl][0], a0, a1, a2, a3, b[dy][0]);
                            mma16(c[rl][1], a0, a1, a2, a3, b[dy][1]);
                        }
                    }
                }
            }
        }

        // ---- Epilogue: direct stores (sector-perfect STG.32)
        #pragma unroll
        for (int j = 0; j < 2; j++) {
            int oc0 = (nth * 2 + j) * 8 + 2 * t;
            float b0 = bg[oc0], b1 = bg[oc0 + 1];
            #pragma unroll
            for (int rl = 0; rl < 4; rl++) {
                float* o = out + (((size_t)(n * OCN + oc0)) << 16)
                               + ((size_t)(y + rl) << 8) + gx;
                o[0]                     = c[rl][j][0] + b0;
                o[(size_t)1 << 16]       = c[rl][j][1] + b1;
                o[8]                     = c[rl][j][2] + b0;
                o[((size_t)1 << 16) + 8] = c[rl][j][3] + b1;
            }
        }
    }
}

extern "C" void kernel_launch(void* const* d_in, const int* in_sizes, int n_in,
                              void* d_out, int out_size) {
    const float* x = (const float*)d_in[0];
    const float* w = (const float*)d_in[1];
    const float* b = (const float*)d_in[2];
    float* out = (float*)d_out;

    cudaFuncSetAttribute(conv3x3_f16_r11_kernel,
                         cudaFuncAttributeMaxDynamicSharedMemorySize, SMEM_TOTAL);

    dim3 grid(HW / SW, HW / YCH, 16);   // (4, 16, 16) = 1024 CTAs
    conv3x3_f16_r11_kernel<<<grid, 256, SMEM_TOTAL>>>(x, w, b, out);
}

// round 12
// speedup vs baseline: 1.5707x; 1.5707x over previous
#include <cuda_runtime.h>
#include <cuda_fp16.h>
#include <cstdint>

// 3x3 s1 p1 conv, NCHW fp32 via mma.sync.m16n8k16 FP16 (f32 accumulate).
// R10 compute core (92.6 us: 4-row warp phases, ring-of-6, 46 KB smem,
// 3 CTAs/SM via launch_bounds(256,3)) made PERSISTENT:
//  - grid = 444 CTAs = 148 SMs x 3 (perfect slot packing, no partial wave)
//  - each CTA statically strides over 2048 fine tiles (64 px x 8 rows x 1 img)
//    -> max 5 tiles/CTA: wave-quantization idle drops from ~23% to ~4%
//  - weights staged ONCE per CTA (was once per tile-CTA)
// Warp = 1 m-tile (16 px) x 2 n-tiles (16 oc) x 4 rows per phase (C=32 regs).
// A: half2-packed [ic/2][px], stride 72 (conflict-free LDS.32 gathers).
// Direct sector-perfect STG.32 epilogue.

#define HW     256
#define ICN    32
#define OCN    32
#define SW     64            // tile strip width
#define YCH    8             // output rows per tile
#define NTILES 2048          // (256/SW) * (256/YCH) * 16 images
#define NCTA   444           // 148 SMs * 3 resident CTAs
#define XW     66            // strip + halo
#define STRIDE 72            // u32 per kp row (==8 mod 32 -> conflict-free)
#define KPN    16            // ic/2 packed rows
#define SLOT_U (KPN * STRIDE)              // 1152 u32 = 4608 B
#define B_BYTES (9 * 2 * 4 * 32 * 8)       // 18432
#define SM_A    B_BYTES
#define NSLOT   6
#define SMEM_TOTAL (B_BYTES + NSLOT * SLOT_U * 4)   // 46080 B

__device__ __forceinline__ uint32_t pack_h2(float a, float b) {
    uint32_t r;
    asm("cvt.rn.f16x2.f32 %0, %2, %1;" : "=r"(r) : "f"(a), "f"(b));
    return r;   // lo half = a, hi half = b
}

__device__ __forceinline__ void mma16(float c[4], uint32_t a0, uint32_t a1,
                                      uint32_t a2, uint32_t a3, uint2 b) {
    asm volatile(
        "mma.sync.aligned.m16n8k16.row.col.f32.f16.f16.f32 "
        "{%0,%1,%2,%3},{%4,%5,%6,%7},{%8,%9},{%0,%1,%2,%3};"
        : "+f"(c[0]), "+f"(c[1]), "+f"(c[2]), "+f"(c[3])
        : "r"(a0), "r"(a1), "r"(a2), "r"(a3), "r"(b.x), "r"(b.y));
}

// Stage input row yin into ring slot (yin mod 6): half2-packed [ic/2][px].
__device__ __forceinline__ void build_row(const float* __restrict__ xn, int yin,
                                          int x0, uint32_t* __restrict__ smA,
                                          int tid) {
    uint32_t* slot = smA + ((yin + 2 * NSLOT) % NSLOT) * SLOT_U;
    bool yok = ((unsigned)yin < HW);
    const float* xr = xn + ((size_t)yin << 8);
    #pragma unroll
    for (int e = tid; e < KPN * XW; e += 256) {
        int kp = e / XW;
        int px = e - kp * XW;
        int gx = x0 - 1 + px;
        float v0 = 0.f, v1 = 0.f;
        if (yok && (unsigned)gx < HW) {
            const float* p = xr + (((size_t)kp * 2) << 16) + gx;
            v0 = p[0];
            v1 = p[1 << 16];
        }
        slot[kp * STRIDE + px] = pack_h2(v0, v1);
    }
}

__global__ __launch_bounds__(256, 3)
void conv3x3_f16_pers_kernel(const float* __restrict__ xg,
                             const float* __restrict__ wg,
                             const float* __restrict__ bg,
                             float* __restrict__ out)
{
    extern __shared__ char smem[];
    uint32_t* smA = (uint32_t*)(smem + SM_A);
    const int tid  = threadIdx.x;
    const int warp = tid >> 5;
    const int lane = tid & 31;
    const int mt   = warp >> 1;     // m-tile 0..3
    const int nth  = warp & 1;      // n-tile half

    // ---- Stage B (fragment order): 2304 uint2 frags, ONCE per persistent CTA
    #pragma unroll
    for (int it = 0; it < 9; it++) {
        int idx  = tid + it * 256;
        int l    = idx & 31;
        int nt   = (idx >> 5) & 3;
        int k0   = (idx >> 7) & 1;
        int tap  = idx >> 8;                    // dy*3+dx
        int oc   = nt * 8 + (l >> 2);
        int ic0  = k0 * 16 + (l & 3) * 2;
        const float* wp = wg + (size_t)oc * ICN * 9 + tap;
        uint2 w2;
        w2.x = pack_h2(wp[(size_t)ic0 * 9],       wp[(size_t)(ic0 + 1) * 9]);
        w2.y = pack_h2(wp[(size_t)(ic0 + 8) * 9], wp[(size_t)(ic0 + 9) * 9]);
        *(uint2*)(smem + ((((tap * 2 + k0) * 4 + nt) * 32 + l) << 3)) = w2;
    }

    const int t = lane & 3, g = lane >> 2;
    const uint2* bw = (const uint2*)smem + lane;
    const uint32_t lbase = t * STRIDE + mt * 16 + g;

    // ---- Persistent tile loop: static stride over 2048 tiles
    #pragma unroll 1
    for (int tile = blockIdx.x; tile < NTILES; tile += NCTA) {
        const int x0 = (tile & 3) * SW;
        const int y0 = ((tile >> 2) & 31) * YCH;
        const int n  = tile >> 7;
        const float* xn = xg + (((size_t)n * ICN) << 16);
        const int gx = x0 + mt * 16 + g;

        __syncthreads();                // prior tile's slot readers done
        build_row(xn, y0 - 1, x0, smA, tid);
        build_row(xn, y0,     x0, smA, tid);

        #pragma unroll 1
        for (int p = 0; p < YCH / 4; p++) {
            const int y = y0 + 4 * p;       // rows y .. y+3

            __syncthreads();                // prev phase's LDS reads done
            build_row(xn, y + 1, x0, smA, tid);
            build_row(xn, y + 2, x0, smA, tid);
            build_row(xn, y + 3, x0, smA, tid);
            build_row(xn, y + 4, x0, smA, tid);
            __syncthreads();                // slots y-1 .. y+4 ready

            float c[4][2][4];
            #pragma unroll
            for (int r = 0; r < 4; r++)
                #pragma unroll
                for (int j = 0; j < 2; j++)
                    #pragma unroll
                    for (int i = 0; i < 4; i++) c[r][j][i] = 0.f;

            uint32_t so[NSLOT];
            #pragma unroll
            for (int i = 0; i < NSLOT; i++)
                so[i] = ((y - 1 + i + 2 * NSLOT) % NSLOT) * SLOT_U + lbase;

            #pragma unroll
            for (int k0 = 0; k0 < 2; k0++) {
                #pragma unroll
                for (int dx = 0; dx < 3; dx++) {
                    // cache 6 B frags (3 dy x 2 nt) in regs
                    uint2 b[3][2];
                    #pragma unroll
                    for (int dy = 0; dy < 3; dy++)
                        #pragma unroll
                        for (int j = 0; j < 2; j++)
                            b[dy][j] = bw[(size_t)((((dy * 3 + dx) * 2 + k0) * 4
                                                    + nth * 2 + j)) * 32];

                    const int ao = k0 * 8 * STRIDE + dx;

                    #pragma unroll
                    for (int i = 0; i < NSLOT; i++) {
                        const uint32_t* s = smA + so[i] + ao;
                        uint32_t a0 = s[0], a1 = s[8];
                        uint32_t a2 = s[4 * STRIDE], a3 = s[4 * STRIDE + 8];
                        #pragma unroll
                        for (int dy = 0; dy < 3; dy++) {
                            int rl = i - dy;
                            if (rl >= 0 && rl < 4) {
                                mma16(c[rl][0], a0, a1, a2, a3, b[dy][0]);
                                mma16(c[rl][1], a0, a1, a2, a3, b[dy][1]);
                            }
                        }
                    }
                }
            }

            // ---- Epilogue: direct stores (sector-perfect STG.32)
            #pragma unroll
            for (int j = 0; j < 2; j++) {
                int oc0 = (nth * 2 + j) * 8 + 2 * t;
                float b0 = bg[oc0], b1 = bg[oc0 + 1];
                #pragma unroll
                for (int rl = 0; rl < 4; rl++) {
                    float* o = out + (((size_t)(n * OCN + oc0)) << 16)
                                   + ((size_t)(y + rl) << 8) + gx;
                    o[0]                     = c[rl][j][0] + b0;
                    o[(size_t)1 << 16]       = c[rl][j][1] + b1;
                    o[8]                     = c[rl][j][2] + b0;
                    o[((size_t)1 << 16) + 8] = c[rl][j][3] + b1;
                }
            }
        }
    }
}

extern "C" void kernel_launch(void* const* d_in, const int* in_sizes, int n_in,
                              void* d_out, int out_size) {
    const float* x = (const float*)d_in[0];
    const float* w = (const float*)d_in[1];
    const float* b = (const float*)d_in[2];
    float* out = (float*)d_out;

    cudaFuncSetAttribute(conv3x3_f16_pers_kernel,
                         cudaFuncAttributeMaxDynamicSharedMemorySize, SMEM_TOTAL);

    conv3x3_f16_pers_kernel<<<NCTA, 256, SMEM_TOTAL>>>(x, w, b, out);
}